// round 11
// baseline (speedup 1.0000x reference)
#include <cuda_runtime.h>
#include <cuda_bf16.h>
#include <math.h>

// FFMCell: new_state = state * gamma(t) + x, gamma = exp((-|a| + i b) * t)
// T=4096, TRACE=64, CTX=64.
//
// R11: single fused kernel, grid = T/2, 256 threads, TWO t-tiles per block
// (8 float4-groups/thread). Prologue computes both tiles' factors in
// parallel (threads 0-127 tile A, 128-255 tile B) so the MUFU chain is paid
// once per 8192 elements and no thread idles; barrier count halved vs R10.
// Loop body is the proven JIT body (4 streaming LDG.128 -> FMA -> 2 plain
// STG.128); cs/dec come from smem per iteration to keep regs ~40
// (6 blocks/SM). Plain stores (not __stcs) let L2 absorb write bursts.

__global__ void __launch_bounds__(256, 6) ffm_r11_kernel(
    const float4* __restrict__ sre,
    const float4* __restrict__ sim,
    const float4* __restrict__ xre,
    const float4* __restrict__ xim,
    const float* __restrict__ a,
    const float* __restrict__ b,
    const int* __restrict__ ivec,
    const int* __restrict__ jvec,
    float* __restrict__ out,
    float* __restrict__ out_tail)
{
    const int tid = threadIdx.x;
    const int t0  = blockIdx.x * 2;

    __shared__ float  s_dec[2 * 64];        // [tile][trace row]
    __shared__ float2 s_cs [2 * 64];        // [tile][(cos,sin) per ctx]

    // ---- Prologue: both tiles' factors computed in parallel ---------------
    {
        const int half = tid >> 7;           // 0: tile A, 1: tile B
        const int r    = tid & 127;
        const int tt   = t0 + half;
        const float tf = (float)__ldg(&jvec[tt]);

        if (r < 64) {
            const float th = __ldg(&b[r]) * tf;   // same fp32 product as ref
            float sn, cs;
            sincosf(th, &sn, &cs);
            s_cs[half * 64 + r] = make_float2(cs, sn);
        } else {
            s_dec[half * 64 + (r - 64)] =
                expf(-fabsf(__ldg(&a[r - 64])) * tf);
            if (r == 64 && out_tail != nullptr) {
                out_tail[tt] = (float)(__ldg(&jvec[tt]) + __ldg(&ivec[tt]));
            }
        }
    }
    __syncthreads();

    const float4* s_cs4 = reinterpret_cast<const float4*>(s_cs);
    const int cbase = (tid & 15) << 1;       // float4 index within a tile
    const int tr0   = tid >> 4;              // base trace row 0..15

    float4* __restrict__ out4 = reinterpret_cast<float4*>(out);
    const int gb = t0 * 1024 + tid;          // group base

    #pragma unroll
    for (int it = 0; it < 8; ++it) {
        const int g = gb + it * 256;         // spans both tiles contiguously

        // JIT streaming loads
        const float4 sr = __ldcs(&sre[g]);
        const float4 si = __ldcs(&sim[g]);
        const float4 xr = __ldcs(&xre[g]);
        const float4 xi = __ldcs(&xim[g]);

        // factors: flat layout makes the index simply it*16 / tile*32
        const float  dec = s_dec[it * 16 + tr0];
        const int    cs_i = (it >> 2) * 32 + cbase;
        const float4 csA = s_cs4[cs_i];      // (cos0,sin0,cos1,sin1)
        const float4 csB = s_cs4[cs_i + 1];  // (cos2,sin2,cos3,sin3)

        const float gr0 = dec * csA.x, gi0 = dec * csA.y;
        const float gr1 = dec * csA.z, gi1 = dec * csA.w;
        const float gr2 = dec * csB.x, gi2 = dec * csB.y;
        const float gr3 = dec * csB.z, gi3 = dec * csB.w;

        float4 o0, o1;
        o0.x = fmaf(sr.x, gr0, fmaf(-si.x, gi0, xr.x));
        o0.y = fmaf(sr.x, gi0, fmaf( si.x, gr0, xi.x));
        o0.z = fmaf(sr.y, gr1, fmaf(-si.y, gi1, xr.y));
        o0.w = fmaf(sr.y, gi1, fmaf( si.y, gr1, xi.y));
        o1.x = fmaf(sr.z, gr2, fmaf(-si.z, gi2, xr.z));
        o1.y = fmaf(sr.z, gi2, fmaf( si.z, gr2, xi.z));
        o1.z = fmaf(sr.w, gr3, fmaf(-si.w, gi3, xr.w));
        o1.w = fmaf(sr.w, gi3, fmaf( si.w, gr3, xi.w));

        out4[2 * g]     = o0;                // plain stores: L2 absorbs bursts
        out4[2 * g + 1] = o1;
    }
}

extern "C" void kernel_launch(void* const* d_in, const int* in_sizes, int n_in,
                              void* d_out, int out_size)
{
    const float4* sre = (const float4*)d_in[0];
    const float4* sim = (const float4*)d_in[1];
    const float4* xre = (const float4*)d_in[2];
    const float4* xim = (const float4*)d_in[3];
    const float*  a   = (const float*)d_in[4];
    const float*  b   = (const float*)d_in[5];
    const int*    iv  = (const int*)d_in[6];
    const int*    jv  = (const int*)d_in[7];

    const int T = in_sizes[6];                      // 4096
    const long long N = (long long)in_sizes[0];     // T*TRACE*CTX

    float* out = (float*)d_out;
    float* out_tail = nullptr;
    if ((long long)out_size > 2LL * N) {
        out_tail = out + 2LL * N;
    }

    ffm_r11_kernel<<<T / 2, 256>>>(sre, sim, xre, xim, a, b, iv, jv,
                                   out, out_tail);
}

// round 12
// speedup vs baseline: 1.0969x; 1.0969x over previous
#include <cuda_runtime.h>
#include <cuda_bf16.h>
#include <math.h>

// FFMCell: new_state = state * gamma(t) + x, gamma = exp((-|a| + i b) * t)
// T=4096, TRACE=64, CTX=64.
//
// R12: single kernel, grid = T, 256 threads, 4 float4-groups/thread (R10
// layout) but factors are WARP-PRIVATE: no smem, no __syncthreads, no
// second kernel. Each warp covers 128 elements (8 trace rows x 64 ctx);
// each lane computes sincos for 2 ctx columns (+ lanes 0-7 one exp each)
// and values are distributed with __shfl_sync. The MUFU chain is per-warp
// and is hidden by co-resident warps exactly like memory latency. Hot body
// is the proven JIT float4 body with plain stores.

__global__ void __launch_bounds__(256, 5) ffm_r12_kernel(
    const float4* __restrict__ sre,
    const float4* __restrict__ sim,
    const float4* __restrict__ xre,
    const float4* __restrict__ xim,
    const float* __restrict__ a,
    const float* __restrict__ b,
    const int* __restrict__ ivec,
    const int* __restrict__ jvec,
    float* __restrict__ out,
    float* __restrict__ out_tail)
{
    const int t    = blockIdx.x;
    const int tid  = threadIdx.x;
    const int lane = tid & 31;
    const unsigned FULL = 0xFFFFFFFFu;

    const float tf = (float)__ldg(&jvec[t]);   // 16KB vector: L1-resident

    // ---- Warp-private factor computation ---------------------------------
    // Lane L computes (cos,sin) for ctx columns 2L and 2L+1.
    float cs0, sn0, cs1, sn1;
    {
        const float th0 = __ldg(&b[2 * lane])     * tf;
        const float th1 = __ldg(&b[2 * lane + 1]) * tf;
        sincosf(th0, &sn0, &cs0);
        sincosf(th1, &sn1, &cs1);
    }
    // Lanes 0-7 compute the 8 decay values this warp needs:
    // row(it, bit) = 16*it + 2*warp + bit, lane L -> it = L>>1, bit = L&1.
    float decv = 0.0f;
    const int wrow2 = (tid >> 5) << 1;          // 2 * (warp index in block)
    if (lane < 8) {
        const int row = ((lane >> 1) << 4) + wrow2 + (lane & 1);
        decv = expf(-fabsf(__ldg(&a[row])) * tf);
    }

    // Gather this thread's 4 ctx columns' (cos,sin) — loop-invariant.
    const int q = tid & 15;                     // ctx quad
    float4 csA, csB;
    csA.x = __shfl_sync(FULL, cs0, 2 * q);
    csA.y = __shfl_sync(FULL, sn0, 2 * q);
    csA.z = __shfl_sync(FULL, cs1, 2 * q);
    csA.w = __shfl_sync(FULL, sn1, 2 * q);
    csB.x = __shfl_sync(FULL, cs0, 2 * q + 1);
    csB.y = __shfl_sync(FULL, sn0, 2 * q + 1);
    csB.z = __shfl_sync(FULL, cs1, 2 * q + 1);
    csB.w = __shfl_sync(FULL, sn1, 2 * q + 1);

    if (tid == 0 && out_tail != nullptr) {
        out_tail[t] = (float)(__ldg(&jvec[t]) + __ldg(&ivec[t]));
    }

    const int decl = (tid >> 4) & 1;            // which row parity I use
    const int g0 = t * 1024 + tid;              // first float4-group
    float4* __restrict__ out4 = reinterpret_cast<float4*>(out);

    #pragma unroll
    for (int it = 0; it < 4; ++it) {
        const int g = g0 + it * 256;

        // JIT streaming loads
        const float4 sr = __ldcs(&sre[g]);
        const float4 si = __ldcs(&sim[g]);
        const float4 xr = __ldcs(&xre[g]);
        const float4 xi = __ldcs(&xim[g]);

        // decay for this iteration's trace row, from the owning lane
        const float dec = __shfl_sync(FULL, decv, 2 * it + decl);

        const float gr0 = dec * csA.x, gi0 = dec * csA.y;
        const float gr1 = dec * csA.z, gi1 = dec * csA.w;
        const float gr2 = dec * csB.x, gi2 = dec * csB.y;
        const float gr3 = dec * csB.z, gi3 = dec * csB.w;

        float4 o0, o1;
        o0.x = fmaf(sr.x, gr0, fmaf(-si.x, gi0, xr.x));
        o0.y = fmaf(sr.x, gi0, fmaf( si.x, gr0, xi.x));
        o0.z = fmaf(sr.y, gr1, fmaf(-si.y, gi1, xr.y));
        o0.w = fmaf(sr.y, gi1, fmaf( si.y, gr1, xi.y));
        o1.x = fmaf(sr.z, gr2, fmaf(-si.z, gi2, xr.z));
        o1.y = fmaf(sr.z, gi2, fmaf( si.z, gr2, xi.z));
        o1.z = fmaf(sr.w, gr3, fmaf(-si.w, gi3, xr.w));
        o1.w = fmaf(sr.w, gi3, fmaf( si.w, gr3, xi.w));

        out4[2 * g]     = o0;
        out4[2 * g + 1] = o1;
    }
}

extern "C" void kernel_launch(void* const* d_in, const int* in_sizes, int n_in,
                              void* d_out, int out_size)
{
    const float4* sre = (const float4*)d_in[0];
    const float4* sim = (const float4*)d_in[1];
    const float4* xre = (const float4*)d_in[2];
    const float4* xim = (const float4*)d_in[3];
    const float*  a   = (const float*)d_in[4];
    const float*  b   = (const float*)d_in[5];
    const int*    iv  = (const int*)d_in[6];
    const int*    jv  = (const int*)d_in[7];

    const int T = in_sizes[6];                      // 4096
    const long long N = (long long)in_sizes[0];     // T*TRACE*CTX

    float* out = (float*)d_out;
    float* out_tail = nullptr;
    if ((long long)out_size > 2LL * N) {
        out_tail = out + 2LL * N;
    }

    ffm_r12_kernel<<<T, 256>>>(sre, sim, xre, xim, a, b, iv, jv,
                               out, out_tail);
}